// round 2
// baseline (speedup 1.0000x reference)
#include <cuda_runtime.h>

// Scratch: transposed weight [G][L] = [8][4096] floats (128 KB)
__device__ float g_wt[8 * 4096];

__global__ void transpose_w_kernel(const float* __restrict__ w) {
    int idx = blockIdx.x * blockDim.x + threadIdx.x;
    if (idx < 8 * 4096) {
        int g = idx >> 12;        // / 4096
        int l = idx & 4095;       // % 4096
        g_wt[idx] = w[l * 8 + g]; // w is [L, G]
    }
}

// One warp handles TWO output rows sharing the same g:
//   r0 = warp_id, r1 = warp_id + 32768   (32768 % 8 == 0 -> same group)
// Each row is 4096 contiguous floats -> perfectly coalesced float4 streams.
// Weight float4 is loaded once and reused for both rows.
__global__ __launch_bounds__(256) void grouped_fc_kernel(
    const float* __restrict__ x,
    const float* __restrict__ bias,
    float* __restrict__ out)
{
    const int warp_global = (blockIdx.x * blockDim.x + threadIdx.x) >> 5; // 0..32767
    const int lane = threadIdx.x & 31;
    const int g = warp_global & 7;

    const float4* __restrict__ xp0 =
        reinterpret_cast<const float4*>(x + (size_t)warp_global * 4096) + lane;
    const float4* __restrict__ xp1 =
        reinterpret_cast<const float4*>(x + ((size_t)warp_global + 32768) * 4096) + lane;
    const float4* __restrict__ wp =
        reinterpret_cast<const float4*>(g_wt + g * 4096) + lane;

    float a0 = 0.f, a1 = 0.f, a2 = 0.f, a3 = 0.f;
    float b0 = 0.f, b1 = 0.f, b2 = 0.f, b3 = 0.f;

    // 4096 / (32 lanes * 4) = 32 iterations.
    #pragma unroll 8
    for (int i = 0; i < 32; i++) {
        float4 xv0 = __ldcs(xp0 + i * 32);   // streaming: read-once data
        float4 xv1 = __ldcs(xp1 + i * 32);
        float4 wv  = wp[i * 32];             // cached: hot in L1/L2
        a0 = fmaf(xv0.x, wv.x, a0);
        a1 = fmaf(xv0.y, wv.y, a1);
        a2 = fmaf(xv0.z, wv.z, a2);
        a3 = fmaf(xv0.w, wv.w, a3);
        b0 = fmaf(xv1.x, wv.x, b0);
        b1 = fmaf(xv1.y, wv.y, b1);
        b2 = fmaf(xv1.z, wv.z, b2);
        b3 = fmaf(xv1.w, wv.w, b3);
    }

    float s0 = (a0 + a1) + (a2 + a3);
    float s1 = (b0 + b1) + (b2 + b3);
    #pragma unroll
    for (int off = 16; off > 0; off >>= 1) {
        s0 += __shfl_xor_sync(0xFFFFFFFFu, s0, off);
        s1 += __shfl_xor_sync(0xFFFFFFFFu, s1, off);
    }

    if (lane == 0) {
        float bv = __ldg(&bias[g]);
        out[warp_global]         = s0 + bv;
        out[warp_global + 32768] = s1 + bv;
    }
}

extern "C" void kernel_launch(void* const* d_in, const int* in_sizes, int n_in,
                              void* d_out, int out_size) {
    const float* x      = (const float*)d_in[0]; // [8192, 8, 4096]
    const float* weight = (const float*)d_in[1]; // [1, 4096, 8]
    const float* bias   = (const float*)d_in[2]; // [8]
    float* out          = (float*)d_out;         // [8192, 8]

    transpose_w_kernel<<<(8 * 4096 + 255) / 256, 256>>>(weight);

    // 32768 warps, 8 per block -> 4096 blocks.
    grouped_fc_kernel<<<4096, 256>>>(x, bias, out);
}